// round 1
// baseline (speedup 1.0000x reference)
#include <cuda_runtime.h>

// Problem constants
// B=8, H=64, W=64, C=256, NUM_HEADS=8, KEY_DIM=32
// M = B*H*W = 32768
#define M_TOT   32768
#define C_DIM   256
#define ELEMS   (M_TOT * C_DIM)   // 8388608

// Scratch buffers (device globals — no allocation allowed)
__device__ __align__(16) float g_q[ELEMS];
__device__ __align__(16) float g_k[ELEMS];
__device__ __align__(16) float g_v[ELEMS];
__device__ __align__(16) float g_lepe[ELEMS];
__device__ __align__(16) float g_v1[ELEMS];
__device__ __align__(16) float g_attn[ELEMS];

// ---------------------------------------------------------------------------
// GEMM: out[m, n] = ( sum_k A[m,k] * W[n,k]  + bias[n] ) * scale
// Optionally A := A + A2 elementwise (for final projection input attn+lepe).
// A: M x 256 row-major, W: 256 x 256 row-major.
// Block tile 64x64, K-tile 16, 256 threads, 4x4 micro-tile per thread.
// ---------------------------------------------------------------------------
template <bool ADD2>
__global__ __launch_bounds__(256)
void gemm_kernel(const float* __restrict__ A,
                 const float* __restrict__ A2,
                 const float* __restrict__ Wm,
                 const float* __restrict__ bias,
                 float scale,
                 float* __restrict__ out)
{
    __shared__ float As[16][65];
    __shared__ float Bs[16][65];

    const int tid = threadIdx.x;
    const int m0  = blockIdx.y * 64;
    const int n0  = blockIdx.x * 64;
    const int tm  = tid >> 4;      // 0..15
    const int tn  = tid & 15;      // 0..15

    const int lr  = tid >> 2;        // 0..63 row within tile
    const int lc4 = (tid & 3) << 2;  // 0,4,8,12 within K-tile

    float acc[4][4];
    #pragma unroll
    for (int i = 0; i < 4; i++)
        #pragma unroll
        for (int j = 0; j < 4; j++) acc[i][j] = 0.f;

    for (int k0 = 0; k0 < 256; k0 += 16) {
        float4 av = *(const float4*)(A + (size_t)(m0 + lr) * 256 + k0 + lc4);
        if (ADD2) {
            float4 a2 = *(const float4*)(A2 + (size_t)(m0 + lr) * 256 + k0 + lc4);
            av.x += a2.x; av.y += a2.y; av.z += a2.z; av.w += a2.w;
        }
        float4 bv = *(const float4*)(Wm + (size_t)(n0 + lr) * 256 + k0 + lc4);

        __syncthreads();  // protect previous iteration's reads
        As[lc4 + 0][lr] = av.x; As[lc4 + 1][lr] = av.y;
        As[lc4 + 2][lr] = av.z; As[lc4 + 3][lr] = av.w;
        Bs[lc4 + 0][lr] = bv.x; Bs[lc4 + 1][lr] = bv.y;
        Bs[lc4 + 2][lr] = bv.z; Bs[lc4 + 3][lr] = bv.w;
        __syncthreads();

        #pragma unroll
        for (int kk = 0; kk < 16; kk++) {
            float a[4], b[4];
            #pragma unroll
            for (int i = 0; i < 4; i++) a[i] = As[kk][tm * 4 + i];
            #pragma unroll
            for (int j = 0; j < 4; j++) b[j] = Bs[kk][tn * 4 + j];
            #pragma unroll
            for (int i = 0; i < 4; i++)
                #pragma unroll
                for (int j = 0; j < 4; j++)
                    acc[i][j] += a[i] * b[j];
        }
    }

    #pragma unroll
    for (int i = 0; i < 4; i++) {
        const int m = m0 + tm * 4 + i;
        #pragma unroll
        for (int j = 0; j < 4; j++) {
            const int n = n0 + tn * 4 + j;
            out[(size_t)m * 256 + n] = (acc[i][j] + bias[n]) * scale;
        }
    }
}

// ---------------------------------------------------------------------------
// LePE: 5x5 depthwise conv, stride 1, pad 2, NHWC, per-channel HWIO weights.
// One thread per output element (b,y,x,c) — c contiguous => coalesced.
// ---------------------------------------------------------------------------
__global__ __launch_bounds__(256)
void lepe_kernel(const float* __restrict__ V,
                 const float* __restrict__ Wl,   // (5,5,1,256)
                 const float* __restrict__ bl,
                 float* __restrict__ out)
{
    const int idx = blockIdx.x * 256 + threadIdx.x;
    const int c = idx & 255;
    const int x = (idx >> 8) & 63;
    const int y = (idx >> 14) & 63;
    const int b = idx >> 20;

    float acc = bl[c];
    #pragma unroll
    for (int dy = 0; dy < 5; dy++) {
        const int yy = y + dy - 2;
        if (yy < 0 || yy > 63) continue;
        #pragma unroll
        for (int dx = 0; dx < 5; dx++) {
            const int xx = x + dx - 2;
            if (xx < 0 || xx > 63) continue;
            acc += V[((((b << 6) + yy) << 6) + xx) * 256 + c] *
                   Wl[(dy * 5 + dx) * 256 + c];
        }
    }
    out[idx] = acc;
}

// ---------------------------------------------------------------------------
// Axis attention: for fixed (b, y, n) computes a 64x64x32 attention.
//   base = b*H*W*C + y*y_stride + n*32 ; row r at base + r*row_stride
//   S[q,k] = dot(Q[q], K[k]) + mask[n,q,k]; softmax over k; O = P @ V.
// Width axis : y = h, y_stride = 64*256, row_stride = 256.
// Height axis: y = w, y_stride = 256,    row_stride = 64*256.
// 64 threads per block, thread t owns query row t.
// ---------------------------------------------------------------------------
__global__ __launch_bounds__(64)
void attn_kernel(const float* __restrict__ Q,
                 const float* __restrict__ K,
                 const float* __restrict__ V,
                 const float* __restrict__ mask,  // (8, 64, 64)
                 float* __restrict__ out,
                 int y_stride, int row_stride)
{
    __shared__ float sQ[64][33];
    __shared__ float sK[64][33];
    __shared__ float sV[64][33];
    __shared__ float sS[64][65];

    const int n = blockIdx.x;
    const int y = blockIdx.y;
    const int b = blockIdx.z;
    const int t = threadIdx.x;

    const size_t base = (size_t)b * (64 * 64 * 256) + (size_t)y * y_stride + n * 32;

    // Cooperative load of Q, K, V tiles (64 rows x 32 d each)
    for (int i = t; i < 64 * 32; i += 64) {
        const int r = i >> 5;
        const int d = i & 31;
        const size_t g = base + (size_t)r * row_stride + d;
        sQ[r][d] = Q[g];
        sK[r][d] = K[g];
        sV[r][d] = V[g];
    }
    __syncthreads();

    float qreg[32];
    #pragma unroll
    for (int d = 0; d < 32; d++) qreg[d] = sQ[t][d];

    const float* mrow = mask + ((n << 6) + t) * 64;

    float mx = -1e30f;
    for (int k = 0; k < 64; k++) {
        float s = 0.f;
        #pragma unroll
        for (int d = 0; d < 32; d++) s += qreg[d] * sK[k][d];
        s += mrow[k];
        sS[t][k] = s;
        mx = fmaxf(mx, s);
    }

    float sum = 0.f;
    for (int k = 0; k < 64; k++) {
        const float e = __expf(sS[t][k] - mx);
        sS[t][k] = e;
        sum += e;
    }
    const float inv = 1.f / sum;

    float o[32];
    #pragma unroll
    for (int d = 0; d < 32; d++) o[d] = 0.f;
    for (int k = 0; k < 64; k++) {
        const float p = sS[t][k] * inv;
        #pragma unroll
        for (int d = 0; d < 32; d++) o[d] += p * sV[k][d];
    }

    #pragma unroll
    for (int d = 0; d < 32; d++)
        out[base + (size_t)t * row_stride + d] = o[d];
}

// ---------------------------------------------------------------------------
extern "C" void kernel_launch(void* const* d_in, const int* in_sizes, int n_in,
                              void* d_out, int out_size)
{
    const float* x      = (const float*)d_in[0];
    const float* mask_h = (const float*)d_in[1];
    const float* mask_w = (const float*)d_in[2];
    const float* Wq = (const float*)d_in[3];
    const float* bq = (const float*)d_in[4];
    const float* Wk = (const float*)d_in[5];
    const float* bk = (const float*)d_in[6];
    const float* Wv = (const float*)d_in[7];
    const float* bv = (const float*)d_in[8];
    const float* Wl = (const float*)d_in[9];
    const float* bl = (const float*)d_in[10];
    const float* Wo = (const float*)d_in[11];
    const float* bo = (const float*)d_in[12];
    float* out = (float*)d_out;

    float *q, *k, *v, *lepe, *v1, *attn;
    cudaGetSymbolAddress((void**)&q,    g_q);
    cudaGetSymbolAddress((void**)&k,    g_k);
    cudaGetSymbolAddress((void**)&v,    g_v);
    cudaGetSymbolAddress((void**)&lepe, g_lepe);
    cudaGetSymbolAddress((void**)&v1,   g_v1);
    cudaGetSymbolAddress((void**)&attn, g_attn);

    const float scaling = 0.17677669529663687f;  // 32^-0.5

    dim3 gemm_grid(C_DIM / 64, M_TOT / 64);  // (4, 512)

    // QKV projections
    gemm_kernel<false><<<gemm_grid, 256>>>(x, nullptr, Wq, bq, 1.0f, q);
    gemm_kernel<false><<<gemm_grid, 256>>>(x, nullptr, Wk, bk, scaling, k);
    gemm_kernel<false><<<gemm_grid, 256>>>(x, nullptr, Wv, bv, 1.0f, v);

    // LePE depthwise conv on v
    lepe_kernel<<<ELEMS / 256, 256>>>(v, Wl, bl, lepe);

    // Width-axis attention: grid (n, h, b); rows along W (stride 256)
    dim3 attn_grid(8, 64, 8);
    attn_kernel<<<attn_grid, 64>>>(q, k, v, mask_w, v1,
                                   /*y_stride=*/64 * 256, /*row_stride=*/256);

    // Height-axis attention: grid (n, w, b); rows along H (stride 64*256)
    attn_kernel<<<attn_grid, 64>>>(q, k, v1, mask_h, attn,
                                   /*y_stride=*/256, /*row_stride=*/64 * 256);

    // Output projection on (attn + lepe)
    gemm_kernel<true><<<gemm_grid, 256>>>(attn, lepe, Wo, bo, 1.0f, out);
}

// round 3
// speedup vs baseline: 1.4988x; 1.4988x over previous
#include <cuda_runtime.h>
#include <cuda_bf16.h>
#include <cstdint>

// Problem constants: B=8, H=64, W=64, C=256, NUM_HEADS=8, KEY_DIM=32
#define M_TOT   32768
#define C_DIM   256
#define ELEMS   (M_TOT * C_DIM)   // 8388608

// ---------------- scratch (device globals; no allocation allowed) ----------
__device__ __align__(16) float g_q[ELEMS];
__device__ __align__(16) float g_k[ELEMS];
__device__ __align__(16) float g_v[ELEMS];
__device__ __align__(16) float g_lepe[ELEMS];
__device__ __align__(16) float g_v1[ELEMS];
__device__ __align__(16) float g_attn[ELEMS];

__device__ __align__(16) __nv_bfloat16 g_ahi[ELEMS];
__device__ __align__(16) __nv_bfloat16 g_alo[ELEMS];
__device__ __align__(16) __nv_bfloat16 g_whi[4 * 65536];
__device__ __align__(16) __nv_bfloat16 g_wlo[4 * 65536];

// ---------------------------------------------------------------------------
// Split fp32 (optionally sum of two fp32 arrays) into bf16 hi/lo pair arrays.
// ---------------------------------------------------------------------------
template <bool TWO>
__global__ __launch_bounds__(256)
void split_kernel(const float* __restrict__ a, const float* __restrict__ b,
                  __nv_bfloat16* __restrict__ hi, __nv_bfloat16* __restrict__ lo,
                  int n4)
{
    int i = blockIdx.x * 256 + threadIdx.x;
    if (i >= n4) return;
    float4 v = ((const float4*)a)[i];
    if (TWO) {
        float4 u = ((const float4*)b)[i];
        v.x += u.x; v.y += u.y; v.z += u.z; v.w += u.w;
    }
    float vv[4] = {v.x, v.y, v.z, v.w};
    uint32_t hp[2], lp[2];
#pragma unroll
    for (int q = 0; q < 2; q++) {
        __nv_bfloat16 h0 = __float2bfloat16(vv[2 * q]);
        __nv_bfloat16 h1 = __float2bfloat16(vv[2 * q + 1]);
        float r0 = vv[2 * q]     - __bfloat162float(h0);
        float r1 = vv[2 * q + 1] - __bfloat162float(h1);
        __nv_bfloat16 l0 = __float2bfloat16(r0);
        __nv_bfloat16 l1 = __float2bfloat16(r1);
        hp[q] = (uint32_t)__bfloat16_as_ushort(h0) |
                ((uint32_t)__bfloat16_as_ushort(h1) << 16);
        lp[q] = (uint32_t)__bfloat16_as_ushort(l0) |
                ((uint32_t)__bfloat16_as_ushort(l1) << 16);
    }
    ((uint2*)hi)[i] = make_uint2(hp[0], hp[1]);
    ((uint2*)lo)[i] = make_uint2(lp[0], lp[1]);
}

// ---------------------------------------------------------------------------
// HMMA (mma.sync m16n8k16 bf16) GEMM with fp32 emulation via hi/lo split:
//   out[m,n] = (sum_k A[m,k]*W[n,k] + bias[n]) * scale
// A: M x 256 (hi/lo bf16, K-major), W: 256 x 256 (hi/lo bf16, K-major).
// CTA tile 128x128, 256 threads = 8 warps in 4(m) x 2(n), warp tile 32x64.
// K chunk = 32 per smem stage.
// ---------------------------------------------------------------------------
__device__ __forceinline__ void mma16816(float* c, const uint32_t* a,
                                         uint32_t b0, uint32_t b1)
{
    asm volatile(
        "mma.sync.aligned.m16n8k16.row.col.f32.bf16.bf16.f32 "
        "{%0,%1,%2,%3}, {%4,%5,%6,%7}, {%8,%9}, {%0,%1,%2,%3};"
        : "+f"(c[0]), "+f"(c[1]), "+f"(c[2]), "+f"(c[3])
        : "r"(a[0]), "r"(a[1]), "r"(a[2]), "r"(a[3]), "r"(b0), "r"(b1));
}

#define SROW 40   // smem row stride in bf16 elems (80 bytes)

__global__ __launch_bounds__(256)
void gemm_hmma(const __nv_bfloat16* __restrict__ Ahi,
               const __nv_bfloat16* __restrict__ Alo,
               const __nv_bfloat16* __restrict__ Bhi,
               const __nv_bfloat16* __restrict__ Blo,
               const float* __restrict__ bias, float scale,
               float* __restrict__ out)
{
    __shared__ __nv_bfloat16 sAh[128][SROW];
    __shared__ __nv_bfloat16 sAl[128][SROW];
    __shared__ __nv_bfloat16 sBh[128][SROW];
    __shared__ __nv_bfloat16 sBl[128][SROW];

    const int tid  = threadIdx.x;
    const int lane = tid & 31;
    const int warp = tid >> 5;
    const int wm   = warp >> 1;   // 0..3
    const int wn   = warp & 1;    // 0..1
    const int m0   = blockIdx.y * 128;
    const int n0   = blockIdx.x * 128;

    const int gid = lane >> 2;          // 0..7
    const int tig = lane & 3;           // 0..3

    float acc[2][8][4];
#pragma unroll
    for (int i = 0; i < 2; i++)
#pragma unroll
        for (int j = 0; j < 8; j++)
#pragma unroll
            for (int t = 0; t < 4; t++) acc[i][j][t] = 0.f;

    const uint4* gAh = (const uint4*)Ahi + (size_t)m0 * 32;
    const uint4* gAl = (const uint4*)Alo + (size_t)m0 * 32;
    const uint4* gBh = (const uint4*)Bhi + (size_t)n0 * 32;
    const uint4* gBl = (const uint4*)Blo + (size_t)n0 * 32;

    for (int kc = 0; kc < 256; kc += 32) {
        const int kq = kc >> 3;   // uint4 offset along K

        // Stage tiles: 128 rows x 32 bf16 (4 uint4/row) each, 512 uint4/tile.
        uint4 vAh[2], vAl[2], vBh[2], vBl[2];
        int rr[2], qq[2];
#pragma unroll
        for (int rep = 0; rep < 2; rep++) {
            const int li = rep * 256 + tid;   // 0..511
            rr[rep] = li >> 2;
            qq[rep] = li & 3;
            const size_t go = (size_t)rr[rep] * 32 + kq + qq[rep];
            vAh[rep] = gAh[go]; vAl[rep] = gAl[go];
            vBh[rep] = gBh[go]; vBl[rep] = gBl[go];
        }
        __syncthreads();   // previous iteration's fragment reads done
#pragma unroll
        for (int rep = 0; rep < 2; rep++) {
            const int r = rr[rep], q8 = qq[rep] * 8;
            *(uint4*)&sAh[r][q8] = vAh[rep];
            *(uint4*)&sAl[r][q8] = vAl[rep];
            *(uint4*)&sBh[r][q8] = vBh[rep];
            *(uint4*)&sBl[r][q8] = vBl[rep];
        }
        __syncthreads();

#pragma unroll
        for (int ks = 0; ks < 2; ks++) {
            const int kb = ks * 16 + tig * 2;

            uint32_t ah[2][4], al[2][4];
#pragma unroll
            for (int i = 0; i < 2; i++) {
                const int row = wm * 32 + i * 16 + gid;
                ah[i][0] = *(const uint32_t*)&sAh[row][kb];
                ah[i][1] = *(const uint32_t*)&sAh[row + 8][kb];
                ah[i][2] = *(const uint32_t*)&sAh[row][kb + 8];
                ah[i][3] = *(const uint32_t*)&sAh[row + 8][kb + 8];
                al[i][0] = *(const uint32_t*)&sAl[row][kb];
                al[i][1] = *(const uint32_t*)&sAl[row + 8][kb];
                al[i][2] = *(const uint32_t*)&sAl[row][kb + 8];
                al[i][3] = *(const uint32_t*)&sAl[row + 8][kb + 8];
            }
#pragma unroll
            for (int j = 0; j < 8; j++) {
                const int n = wn * 64 + j * 8 + gid;
                const uint32_t bh0 = *(const uint32_t*)&sBh[n][kb];
                const uint32_t bh1 = *(const uint32_t*)&sBh[n][kb + 8];
                const uint32_t bl0 = *(const uint32_t*)&sBl[n][kb];
                const uint32_t bl1 = *(const uint32_t*)&sBl[n][kb + 8];
#pragma unroll
                for (int i = 0; i < 2; i++) {
                    mma16816(acc[i][j], ah[i], bh0, bh1);
                    mma16816(acc[i][j], al[i], bh0, bh1);
                    mma16816(acc[i][j], ah[i], bl0, bl1);
                }
            }
        }
    }

    // Epilogue: D[row][col] mapping per m16n8k16 C-fragment layout.
#pragma unroll
    for (int i = 0; i < 2; i++) {
        const int row = m0 + wm * 32 + i * 16 + gid;
#pragma unroll
        for (int j = 0; j < 8; j++) {
            const int col = n0 + wn * 64 + j * 8 + tig * 2;
            const float b0 = bias[col], b1 = bias[col + 1];
            float2 v0 = make_float2((acc[i][j][0] + b0) * scale,
                                    (acc[i][j][1] + b1) * scale);
            float2 v1 = make_float2((acc[i][j][2] + b0) * scale,
                                    (acc[i][j][3] + b1) * scale);
            *(float2*)(out + (size_t)row * 256 + col)       = v0;
            *(float2*)(out + (size_t)(row + 8) * 256 + col) = v1;
        }
    }
}

// ---------------------------------------------------------------------------
// LePE: 5x5 depthwise conv, stride 1, pad 2, NHWC.
// ---------------------------------------------------------------------------
__global__ __launch_bounds__(256)
void lepe_kernel(const float* __restrict__ V,
                 const float* __restrict__ Wl,
                 const float* __restrict__ bl,
                 float* __restrict__ out)
{
    const int idx = blockIdx.x * 256 + threadIdx.x;
    const int c = idx & 255;
    const int x = (idx >> 8) & 63;
    const int y = (idx >> 14) & 63;
    const int b = idx >> 20;

    float acc = bl[c];
#pragma unroll
    for (int dy = 0; dy < 5; dy++) {
        const int yy = y + dy - 2;
        if (yy < 0 || yy > 63) continue;
#pragma unroll
        for (int dx = 0; dx < 5; dx++) {
            const int xx = x + dx - 2;
            if (xx < 0 || xx > 63) continue;
            acc += V[((((b << 6) + yy) << 6) + xx) * 256 + c] *
                   Wl[(dy * 5 + dx) * 256 + c];
        }
    }
    out[idx] = acc;
}

// ---------------------------------------------------------------------------
// Axis attention (fp32): 64x64x32 attention per (b, line, head).
// ---------------------------------------------------------------------------
__global__ __launch_bounds__(64)
void attn_kernel(const float* __restrict__ Q,
                 const float* __restrict__ K,
                 const float* __restrict__ V,
                 const float* __restrict__ mask,
                 float* __restrict__ out,
                 int y_stride, int row_stride)
{
    __shared__ float sQ[64][33];
    __shared__ float sK[64][33];
    __shared__ float sV[64][33];
    __shared__ float sS[64][65];

    const int n = blockIdx.x;
    const int y = blockIdx.y;
    const int b = blockIdx.z;
    const int t = threadIdx.x;

    const size_t base = (size_t)b * (64 * 64 * 256) + (size_t)y * y_stride + n * 32;

    for (int i = t; i < 64 * 32; i += 64) {
        const int r = i >> 5;
        const int d = i & 31;
        const size_t g = base + (size_t)r * row_stride + d;
        sQ[r][d] = Q[g];
        sK[r][d] = K[g];
        sV[r][d] = V[g];
    }
    __syncthreads();

    float qreg[32];
#pragma unroll
    for (int d = 0; d < 32; d++) qreg[d] = sQ[t][d];

    const float* mrow = mask + ((n << 6) + t) * 64;

    float mx = -1e30f;
    for (int k = 0; k < 64; k++) {
        float s = 0.f;
#pragma unroll
        for (int d = 0; d < 32; d++) s += qreg[d] * sK[k][d];
        s += mrow[k];
        sS[t][k] = s;
        mx = fmaxf(mx, s);
    }

    float sum = 0.f;
    for (int k = 0; k < 64; k++) {
        const float e = __expf(sS[t][k] - mx);
        sS[t][k] = e;
        sum += e;
    }
    const float inv = 1.f / sum;

    float o[32];
#pragma unroll
    for (int d = 0; d < 32; d++) o[d] = 0.f;
    for (int k = 0; k < 64; k++) {
        const float p = sS[t][k] * inv;
#pragma unroll
        for (int d = 0; d < 32; d++) o[d] += p * sV[k][d];
    }

#pragma unroll
    for (int d = 0; d < 32; d++)
        out[base + (size_t)t * row_stride + d] = o[d];
}

// ---------------------------------------------------------------------------
extern "C" void kernel_launch(void* const* d_in, const int* in_sizes, int n_in,
                              void* d_out, int out_size)
{
    const float* x      = (const float*)d_in[0];
    const float* mask_h = (const float*)d_in[1];
    const float* mask_w = (const float*)d_in[2];
    const float* Wq = (const float*)d_in[3];
    const float* bq = (const float*)d_in[4];
    const float* Wk = (const float*)d_in[5];
    const float* bk = (const float*)d_in[6];
    const float* Wv = (const float*)d_in[7];
    const float* bv = (const float*)d_in[8];
    const float* Wl = (const float*)d_in[9];
    const float* bl = (const float*)d_in[10];
    const float* Wo = (const float*)d_in[11];
    const float* bo = (const float*)d_in[12];
    float* out = (float*)d_out;

    float *q, *k, *v, *lepe, *v1, *attn;
    __nv_bfloat16 *ahi, *alo, *whi, *wlo;
    cudaGetSymbolAddress((void**)&q,    g_q);
    cudaGetSymbolAddress((void**)&k,    g_k);
    cudaGetSymbolAddress((void**)&v,    g_v);
    cudaGetSymbolAddress((void**)&lepe, g_lepe);
    cudaGetSymbolAddress((void**)&v1,   g_v1);
    cudaGetSymbolAddress((void**)&attn, g_attn);
    cudaGetSymbolAddress((void**)&ahi,  g_ahi);
    cudaGetSymbolAddress((void**)&alo,  g_alo);
    cudaGetSymbolAddress((void**)&whi,  g_whi);
    cudaGetSymbolAddress((void**)&wlo,  g_wlo);

    const float scaling = 0.17677669529663687f;  // 32^-0.5

    // Split activations and weights into bf16 hi/lo.
    split_kernel<false><<<ELEMS / 4 / 256, 256>>>(x, nullptr, ahi, alo, ELEMS / 4);
    split_kernel<false><<<64, 256>>>(Wq, nullptr, whi + 0 * 65536, wlo + 0 * 65536, 16384);
    split_kernel<false><<<64, 256>>>(Wk, nullptr, whi + 1 * 65536, wlo + 1 * 65536, 16384);
    split_kernel<false><<<64, 256>>>(Wv, nullptr, whi + 2 * 65536, wlo + 2 * 65536, 16384);
    split_kernel<false><<<64, 256>>>(Wo, nullptr, whi + 3 * 65536, wlo + 3 * 65536, 16384);

    dim3 ggrid(2, 256);   // 128x128 tiles over 32768x256

    gemm_hmma<<<ggrid, 256>>>(ahi, alo, whi + 0 * 65536, wlo + 0 * 65536, bq, 1.0f, q);
    gemm_hmma<<<ggrid, 256>>>(ahi, alo, whi + 1 * 65536, wlo + 1 * 65536, bk, scaling, k);
    gemm_hmma<<<ggrid, 256>>>(ahi, alo, whi + 2 * 65536, wlo + 2 * 65536, bv, 1.0f, v);

    lepe_kernel<<<ELEMS / 256, 256>>>(v, Wl, bl, lepe);

    dim3 attn_grid(8, 64, 8);
    attn_kernel<<<attn_grid, 64>>>(q, k, v, mask_w, v1,
                                   /*y_stride=*/64 * 256, /*row_stride=*/256);
    attn_kernel<<<attn_grid, 64>>>(q, k, v1, mask_h, attn,
                                   /*y_stride=*/256, /*row_stride=*/64 * 256);

    // Output projection on (attn + lepe)
    split_kernel<true><<<ELEMS / 4 / 256, 256>>>(attn, lepe, ahi, alo, ELEMS / 4);
    gemm_hmma<<<ggrid, 256>>>(ahi, alo, whi + 3 * 65536, wlo + 3 * 65536, bo, 1.0f, out);
}

// round 4
// speedup vs baseline: 2.4662x; 1.6455x over previous
#include <cuda_runtime.h>
#include <cuda_bf16.h>
#include <cstdint>

// Problem constants: B=8, H=64, W=64, C=256, NUM_HEADS=8, KEY_DIM=32
#define M_TOT   32768
#define C_DIM   256
#define ELEMS   (M_TOT * C_DIM)   // 8388608

// ---------------- scratch (device globals; no allocation allowed) ----------
__device__ __align__(16) float g_q[ELEMS];
__device__ __align__(16) float g_k[ELEMS];
__device__ __align__(16) float g_v[ELEMS];
__device__ __align__(16) float g_lepe[ELEMS];
__device__ __align__(16) float g_v1[ELEMS];
__device__ __align__(16) float g_attn[ELEMS];

__device__ __align__(16) __nv_bfloat16 g_ahi[ELEMS];
__device__ __align__(16) __nv_bfloat16 g_alo[ELEMS];
__device__ __align__(16) __nv_bfloat16 g_whi[4 * 65536];
__device__ __align__(16) __nv_bfloat16 g_wlo[4 * 65536];

// ---------------- helpers ----------------------------------------------------
__device__ __forceinline__ uint32_t smem_u32(const void* p) {
    uint32_t a;
    asm("{ .reg .u64 t; cvta.to.shared.u64 t, %1; cvt.u32.u64 %0, t; }"
        : "=r"(a) : "l"(p));
    return a;
}

__device__ __forceinline__ void mma16816(float* c, const uint32_t* a,
                                         uint32_t b0, uint32_t b1)
{
    asm volatile(
        "mma.sync.aligned.m16n8k16.row.col.f32.bf16.bf16.f32 "
        "{%0,%1,%2,%3}, {%4,%5,%6,%7}, {%8,%9}, {%0,%1,%2,%3};"
        : "+f"(c[0]), "+f"(c[1]), "+f"(c[2]), "+f"(c[3])
        : "r"(a[0]), "r"(a[1]), "r"(a[2]), "r"(a[3]), "r"(b0), "r"(b1));
}

__device__ __forceinline__ void ldm_x4(uint32_t* r, uint32_t addr) {
    asm volatile("ldmatrix.sync.aligned.m8n8.x4.shared.b16 {%0,%1,%2,%3}, [%4];"
        : "=r"(r[0]), "=r"(r[1]), "=r"(r[2]), "=r"(r[3]) : "r"(addr));
}

// ---------------------------------------------------------------------------
// Split fp32 (optionally sum of two fp32 arrays) into bf16 hi/lo pair arrays.
// ---------------------------------------------------------------------------
template <bool TWO>
__global__ __launch_bounds__(256)
void split_kernel(const float* __restrict__ a, const float* __restrict__ b,
                  __nv_bfloat16* __restrict__ hi, __nv_bfloat16* __restrict__ lo,
                  int n4)
{
    int i = blockIdx.x * 256 + threadIdx.x;
    if (i >= n4) return;
    float4 v = ((const float4*)a)[i];
    if (TWO) {
        float4 u = ((const float4*)b)[i];
        v.x += u.x; v.y += u.y; v.z += u.z; v.w += u.w;
    }
    float vv[4] = {v.x, v.y, v.z, v.w};
    uint32_t hp[2], lp[2];
#pragma unroll
    for (int q = 0; q < 2; q++) {
        __nv_bfloat16 h0 = __float2bfloat16(vv[2 * q]);
        __nv_bfloat16 h1 = __float2bfloat16(vv[2 * q + 1]);
        float r0 = vv[2 * q]     - __bfloat162float(h0);
        float r1 = vv[2 * q + 1] - __bfloat162float(h1);
        __nv_bfloat16 l0 = __float2bfloat16(r0);
        __nv_bfloat16 l1 = __float2bfloat16(r1);
        hp[q] = (uint32_t)__bfloat16_as_ushort(h0) |
                ((uint32_t)__bfloat16_as_ushort(h1) << 16);
        lp[q] = (uint32_t)__bfloat16_as_ushort(l0) |
                ((uint32_t)__bfloat16_as_ushort(l1) << 16);
    }
    ((uint2*)hi)[i] = make_uint2(hp[0], hp[1]);
    ((uint2*)lo)[i] = make_uint2(lp[0], lp[1]);
}

// ---------------------------------------------------------------------------
// HMMA GEMM, fp32 emulation (hi/lo bf16, 3 products), cp.async double buffer,
// ldmatrix fragment loads.
//   out[m,n] = (sum_k A[m,k]*W[n,k] + bias[n]) * scale
// CTA tile 128x128, 8 warps 4(m)x2(n), warp tile 32x64, K chunk 32, 2 stages.
// Tile layout in smem: 128 rows x 32 bf16, row stride 80 B.
// ---------------------------------------------------------------------------
#define TILE_B  10240         // 128 * 80
#define STAGE_B (4 * TILE_B)  // Ah, Al, Bh, Bl
#define GEMM_SMEM (2 * STAGE_B)

__global__ __launch_bounds__(256)
void gemm_hmma(const __nv_bfloat16* __restrict__ Ahi,
               const __nv_bfloat16* __restrict__ Alo,
               const __nv_bfloat16* __restrict__ Bhi,
               const __nv_bfloat16* __restrict__ Blo,
               const float* __restrict__ bias, float scale,
               float* __restrict__ out)
{
    extern __shared__ __align__(16) char gsm[];

    const int tid  = threadIdx.x;
    const int lane = tid & 31;
    const int warp = tid >> 5;
    const int wm   = warp >> 1;   // 0..3
    const int wn   = warp & 1;    // 0..1
    const int m0   = blockIdx.y * 128;
    const int n0   = blockIdx.x * 128;
    const int gid  = lane >> 2;
    const int tig  = lane & 3;

    float acc[2][8][4];
#pragma unroll
    for (int i = 0; i < 2; i++)
#pragma unroll
        for (int j = 0; j < 8; j++)
#pragma unroll
            for (int t = 0; t < 4; t++) acc[i][j][t] = 0.f;

    const uint4* gsrc[4] = { (const uint4*)Ahi + (size_t)m0 * 32,
                             (const uint4*)Alo + (size_t)m0 * 32,
                             (const uint4*)Bhi + (size_t)n0 * 32,
                             (const uint4*)Blo + (size_t)n0 * 32 };
    const uint32_t smem_base = smem_u32(gsm);

    // issue cp.async loads for one K-chunk into one stage
    auto issue = [&](int chunk, int stg) {
        const int kq4 = chunk * 4;
        const uint32_t sb = smem_base + stg * STAGE_B;
#pragma unroll
        for (int tl = 0; tl < 4; tl++) {
#pragma unroll
            for (int rep = 0; rep < 2; rep++) {
                const int li = rep * 256 + tid;
                const int r = li >> 2, qd = li & 3;
                const uint4* src = gsrc[tl] + (size_t)r * 32 + kq4 + qd;
                const uint32_t dst = sb + tl * TILE_B + r * 80 + qd * 16;
                asm volatile("cp.async.ca.shared.global [%0], [%1], 16;"
                             :: "r"(dst), "l"(src));
            }
        }
    };

    issue(0, 0);
    asm volatile("cp.async.commit_group;" ::: "memory");

    for (int c = 0; c < 8; c++) {
        if (c + 1 < 8) issue(c + 1, (c + 1) & 1);
        asm volatile("cp.async.commit_group;" ::: "memory");
        asm volatile("cp.async.wait_group 1;" ::: "memory");
        __syncthreads();

        const uint32_t sb = smem_base + (c & 1) * STAGE_B;
        const uint32_t sAh = sb, sAl = sb + TILE_B;
        const uint32_t sBh = sb + 2 * TILE_B, sBl = sb + 3 * TILE_B;

#pragma unroll
        for (int ks = 0; ks < 2; ks++) {
            const int kb = ks * 16;
            uint32_t ah[2][4], al[2][4];
            const int arow = wm * 32 + (lane & 15);
            const int acol = kb + ((lane >> 4) << 3);
#pragma unroll
            for (int i = 0; i < 2; i++) {
                const uint32_t off = (uint32_t)((arow + i * 16) * 80 + acol * 2);
                ldm_x4(ah[i], sAh + off);
                ldm_x4(al[i], sAl + off);
            }
            const int brow0 = wn * 64 + ((lane >> 4) & 1) * 8 + (lane & 7);
            const int bcol  = kb + ((lane >> 3) & 1) * 8;
#pragma unroll
            for (int jp = 0; jp < 4; jp++) {
                uint32_t bh[4], bl[4];
                const uint32_t off = (uint32_t)((brow0 + jp * 16) * 80 + bcol * 2);
                ldm_x4(bh, sBh + off);
                ldm_x4(bl, sBl + off);
#pragma unroll
                for (int jj = 0; jj < 2; jj++) {
                    const int j = jp * 2 + jj;
#pragma unroll
                    for (int i = 0; i < 2; i++) {
                        mma16816(acc[i][j], ah[i], bh[jj * 2], bh[jj * 2 + 1]);
                        mma16816(acc[i][j], al[i], bh[jj * 2], bh[jj * 2 + 1]);
                        mma16816(acc[i][j], ah[i], bl[jj * 2], bl[jj * 2 + 1]);
                    }
                }
            }
        }
        __syncthreads();
    }

    // Epilogue
#pragma unroll
    for (int i = 0; i < 2; i++) {
        const int row = m0 + wm * 32 + i * 16 + gid;
#pragma unroll
        for (int j = 0; j < 8; j++) {
            const int col = n0 + wn * 64 + j * 8 + tig * 2;
            const float b0 = bias[col], b1 = bias[col + 1];
            float2 v0 = make_float2((acc[i][j][0] + b0) * scale,
                                    (acc[i][j][1] + b1) * scale);
            float2 v1 = make_float2((acc[i][j][2] + b0) * scale,
                                    (acc[i][j][3] + b1) * scale);
            *(float2*)(out + (size_t)row * 256 + col)       = v0;
            *(float2*)(out + (size_t)(row + 8) * 256 + col) = v1;
        }
    }
}

// ---------------------------------------------------------------------------
// LePE: 5x5 depthwise conv, register-blocked 4 x-outputs per thread.
// ---------------------------------------------------------------------------
__global__ __launch_bounds__(256)
void lepe_kernel(const float* __restrict__ V,
                 const float* __restrict__ Wl,
                 const float* __restrict__ bl,
                 float* __restrict__ out)
{
    const int idx = blockIdx.x * 256 + threadIdx.x;
    const int c  = idx & 255;
    const int xg = (idx >> 8) & 15;
    const int y  = (idx >> 12) & 63;
    const int b  = idx >> 18;
    const int x0 = xg * 4;

    float w[5][5];
#pragma unroll
    for (int dy = 0; dy < 5; dy++)
#pragma unroll
        for (int dx = 0; dx < 5; dx++)
            w[dy][dx] = Wl[(dy * 5 + dx) * 256 + c];

    const float bias = bl[c];
    float acc[4] = {bias, bias, bias, bias};

#pragma unroll
    for (int dy = 0; dy < 5; dy++) {
        const int yy = y + dy - 2;
        if (yy < 0 || yy > 63) continue;
        const float* vrow = V + (size_t)(((b << 6) + yy) << 6) * 256 + c;
#pragma unroll
        for (int e = 0; e < 8; e++) {
            const int xx = x0 - 2 + e;
            if (xx < 0 || xx > 63) continue;
            const float val = vrow[(size_t)xx * 256];
#pragma unroll
            for (int u = 0; u < 4; u++) {
                const int dxi = e - u;
                if (dxi >= 0 && dxi < 5) acc[u] += val * w[dy][dxi];
            }
        }
    }

    float* orow = out + (size_t)((((b << 6) + y) << 6) + x0) * 256 + c;
#pragma unroll
    for (int u = 0; u < 4; u++) orow[(size_t)u * 256] = acc[u];
}

// ---------------------------------------------------------------------------
// Axis attention (fp32): 64x64x32 per (b, line, head).
// K/V rows as float4 smem broadcasts; Q and O in registers; S in padded smem.
// ---------------------------------------------------------------------------
__global__ __launch_bounds__(64)
void attn_kernel(const float* __restrict__ Q,
                 const float* __restrict__ K,
                 const float* __restrict__ V,
                 const float* __restrict__ mask,
                 float* __restrict__ out,
                 int y_stride, int row_stride)
{
    __shared__ float4 sK[64][8];
    __shared__ float4 sV[64][8];
    __shared__ float  sS[64][65];

    const int n = blockIdx.x;
    const int y = blockIdx.y;
    const int b = blockIdx.z;
    const int t = threadIdx.x;

    const size_t base = (size_t)b * (64 * 64 * 256) + (size_t)y * y_stride + n * 32;

    for (int i = t; i < 512; i += 64) {
        const int r = i >> 3, j = i & 7;
        const float4* kp = (const float4*)(K + base + (size_t)r * row_stride) + j;
        const float4* vp = (const float4*)(V + base + (size_t)r * row_stride) + j;
        sK[r][j] = *kp;
        sV[r][j] = *vp;
    }

    float4 q[8];
    {
        const float4* qp = (const float4*)(Q + base + (size_t)t * row_stride);
#pragma unroll
        for (int j = 0; j < 8; j++) q[j] = qp[j];
    }
    __syncthreads();

#pragma unroll 4
    for (int k = 0; k < 64; k++) {
        float s = 0.f;
#pragma unroll
        for (int j = 0; j < 8; j++) {
            const float4 kv = sK[k][j];
            s += q[j].x * kv.x + q[j].y * kv.y + q[j].z * kv.z + q[j].w * kv.w;
        }
        sS[t][k] = s;
    }

    // mask add + row max
    const float4* mrow = (const float4*)(mask + ((size_t)((n << 6) + t)) * 64);
    float mx = -1e30f;
#pragma unroll
    for (int j = 0; j < 16; j++) {
        const float4 m = mrow[j];
        float s0 = sS[t][4 * j + 0] + m.x;
        float s1 = sS[t][4 * j + 1] + m.y;
        float s2 = sS[t][4 * j + 2] + m.z;
        float s3 = sS[t][4 * j + 3] + m.w;
        sS[t][4 * j + 0] = s0; sS[t][4 * j + 1] = s1;
        sS[t][4 * j + 2] = s2; sS[t][4 * j + 3] = s3;
        mx = fmaxf(mx, fmaxf(fmaxf(s0, s1), fmaxf(s2, s3)));
    }

    float sum = 0.f;
#pragma unroll 8
    for (int k = 0; k < 64; k++) {
        const float e = __expf(sS[t][k] - mx);
        sS[t][k] = e;
        sum += e;
    }
    const float inv = 1.f / sum;

    float4 o[8];
#pragma unroll
    for (int j = 0; j < 8; j++) o[j] = make_float4(0.f, 0.f, 0.f, 0.f);

#pragma unroll 2
    for (int k = 0; k < 64; k++) {
        const float p = sS[t][k] * inv;
#pragma unroll
        for (int j = 0; j < 8; j++) {
            const float4 vv = sV[k][j];
            o[j].x += p * vv.x; o[j].y += p * vv.y;
            o[j].z += p * vv.z; o[j].w += p * vv.w;
        }
    }

    float4* op = (float4*)(out + base + (size_t)t * row_stride);
#pragma unroll
    for (int j = 0; j < 8; j++) op[j] = o[j];
}

// ---------------------------------------------------------------------------
extern "C" void kernel_launch(void* const* d_in, const int* in_sizes, int n_in,
                              void* d_out, int out_size)
{
    const float* x      = (const float*)d_in[0];
    const float* mask_h = (const float*)d_in[1];
    const float* mask_w = (const float*)d_in[2];
    const float* Wq = (const float*)d_in[3];
    const float* bq = (const float*)d_in[4];
    const float* Wk = (const float*)d_in[5];
    const float* bk = (const float*)d_in[6];
    const float* Wv = (const float*)d_in[7];
    const float* bv = (const float*)d_in[8];
    const float* Wl = (const float*)d_in[9];
    const float* bl = (const float*)d_in[10];
    const float* Wo = (const float*)d_in[11];
    const float* bo = (const float*)d_in[12];
    float* out = (float*)d_out;

    float *q, *k, *v, *lepe, *v1, *attn;
    __nv_bfloat16 *ahi, *alo, *whi, *wlo;
    cudaGetSymbolAddress((void**)&q,    g_q);
    cudaGetSymbolAddress((void**)&k,    g_k);
    cudaGetSymbolAddress((void**)&v,    g_v);
    cudaGetSymbolAddress((void**)&lepe, g_lepe);
    cudaGetSymbolAddress((void**)&v1,   g_v1);
    cudaGetSymbolAddress((void**)&attn, g_attn);
    cudaGetSymbolAddress((void**)&ahi,  g_ahi);
    cudaGetSymbolAddress((void**)&alo,  g_alo);
    cudaGetSymbolAddress((void**)&whi,  g_whi);
    cudaGetSymbolAddress((void**)&wlo,  g_wlo);

    static int smem_set = 0;
    if (!smem_set) {
        cudaFuncSetAttribute(gemm_hmma,
                             cudaFuncAttributeMaxDynamicSharedMemorySize,
                             GEMM_SMEM);
        smem_set = 1;
    }

    const float scaling = 0.17677669529663687f;  // 32^-0.5

    split_kernel<false><<<ELEMS / 4 / 256, 256>>>(x, nullptr, ahi, alo, ELEMS / 4);
    split_kernel<false><<<64, 256>>>(Wq, nullptr, whi + 0 * 65536, wlo + 0 * 65536, 16384);
    split_kernel<false><<<64, 256>>>(Wk, nullptr, whi + 1 * 65536, wlo + 1 * 65536, 16384);
    split_kernel<false><<<64, 256>>>(Wv, nullptr, whi + 2 * 65536, wlo + 2 * 65536, 16384);
    split_kernel<false><<<64, 256>>>(Wo, nullptr, whi + 3 * 65536, wlo + 3 * 65536, 16384);

    dim3 ggrid(2, 256);

    gemm_hmma<<<ggrid, 256, GEMM_SMEM>>>(ahi, alo, whi + 0 * 65536, wlo + 0 * 65536,
                                         bq, 1.0f, q);
    gemm_hmma<<<ggrid, 256, GEMM_SMEM>>>(ahi, alo, whi + 1 * 65536, wlo + 1 * 65536,
                                         bk, scaling, k);
    gemm_hmma<<<ggrid, 256, GEMM_SMEM>>>(ahi, alo, whi + 2 * 65536, wlo + 2 * 65536,
                                         bv, 1.0f, v);

    lepe_kernel<<<ELEMS / 4 / 256, 256>>>(v, Wl, bl, lepe);

    dim3 attn_grid(8, 64, 8);
    attn_kernel<<<attn_grid, 64>>>(q, k, v, mask_w, v1,
                                   /*y_stride=*/64 * 256, /*row_stride=*/256);
    attn_kernel<<<attn_grid, 64>>>(q, k, v1, mask_h, attn,
                                   /*y_stride=*/256, /*row_stride=*/64 * 256);

    split_kernel<true><<<ELEMS / 4 / 256, 256>>>(attn, lepe, ahi, alo, ELEMS / 4);
    gemm_hmma<<<ggrid, 256, GEMM_SMEM>>>(ahi, alo, whi + 3 * 65536, wlo + 3 * 65536,
                                         bo, 1.0f, out);
}